// round 14
// baseline (speedup 1.0000x reference)
#include <cuda_runtime.h>
#include <cuda_fp16.h>
#include <cstdint>
#include <cstddef>

// ---------------- problem constants ----------------
#define SEQ   2048
#define BATCH 16
#define DIN   512
#define HID   512
#define MROWS (SEQ*BATCH)      // 32768 rows (s*16+b)
#define NDIR  (3*HID)          // 1536 gate cols per direction
#define NCOLS (2*NDIR)         // 3072 combined
#define XCNT  ((size_t)MROWS*DIN)

// ---------------- GEMM tiling (fp16 mma m16n8k16, f16 acc + fp32 spill) ----------------
#define BM 128                 // = 8 seq steps x 16 batch
#define BN 96                  // 32 h * 3 gates (z,f,o interleaved)
#define BK 64                  // halves per k-tile (128B rows)
#define KTILES (DIN/BK)        // 8
#define NTHREADS 256
#define NSTAGE 3
#define STAGE_BYTES ((BM+BN)*BK*2)            // 28672
#define SMEM_BYTES  (NSTAGE*STAGE_BYTES)      // 86016 (epilogue reuse 128*100*4=51200)
#define EPIPITCH 100

// ---------------- scan chunking ----------------
#define NCH     16384          // dir*8192 + b*512 + h
#define NCHUNK  256            // chunks of 8 steps (one per m-tile)
#define NSUPER  16             // superchunks of 16 chunks (128 steps)
#define SSTRIDE (BATCH*2*HID)  // per-s element stride in g_ph/g_o/out (16384)

// ---------------- device scratch ----------------
__device__ __half  g_Xh[XCNT];                       // fp16 X
__device__ __half  g_Wh[(size_t)NCOLS * DIN];        // fp16 permuted [dir][h*3+g]
__device__ __half2 g_ph[(size_t)MROWS * 2 * HID];    // (P=prefix prod a, H=local h)
__device__ __half  g_o[(size_t)MROWS * 2 * HID];     // o gate
__device__ float2  g_AC[(size_t)NCH * NCHUNK];       // per-chunk (A,C), [ch][chunk]
__device__ float   g_hsup[(size_t)NCH * NSUPER];     // h at superchunk start

// ---------------- helpers ----------------
static __device__ __forceinline__ uint32_t smem_u32(const void* p) {
    uint32_t a;
    asm("{ .reg .u64 t; cvta.to.shared.u64 t, %1; cvt.u32.u64 %0, t; }"
        : "=r"(a) : "l"(p));
    return a;
}
static __device__ __forceinline__ void cp_async16(uint32_t saddr, const void* gaddr) {
    asm volatile("cp.async.cg.shared.global [%0], [%1], 16;"
                 :: "r"(saddr), "l"(gaddr) : "memory");
}
static __device__ __forceinline__ void cp_commit() {
    asm volatile("cp.async.commit_group;" ::: "memory");
}
template <int N>
static __device__ __forceinline__ void cp_wait() {
    asm volatile("cp.async.wait_group %0;" :: "n"(N) : "memory");
}
static __device__ __forceinline__ void ldsm_x4(uint32_t* r, uint32_t addr) {
    asm volatile("ldmatrix.sync.aligned.m8n8.x4.shared.b16 {%0,%1,%2,%3}, [%4];"
                 : "=r"(r[0]), "=r"(r[1]), "=r"(r[2]), "=r"(r[3]) : "r"(addr));
}
// fp16-accumulator mma: D/C are 2 x .f16x2 regs. Layout matches f32-acc variant:
// reg0 = (c0,c1) row gid, reg1 = (c2,c3) row gid+8.
static __device__ __forceinline__ void mma_f16acc(uint32_t* d, const uint32_t* a,
                                                  uint32_t b0, uint32_t b1) {
    asm volatile(
        "mma.sync.aligned.m16n8k16.row.col.f16.f16.f16.f16 "
        "{%0,%1}, {%2,%3,%4,%5}, {%6,%7}, {%0,%1};"
        : "+r"(d[0]), "+r"(d[1])
        : "r"(a[0]), "r"(a[1]), "r"(a[2]), "r"(a[3]), "r"(b0), "r"(b1));
}
static __device__ __forceinline__ float fast_exp2(float x) {
    float y; asm("ex2.approx.f32 %0, %1;" : "=f"(y) : "f"(x)); return y;
}
static __device__ __forceinline__ float fast_rcp(float x) {
    float y; asm("rcp.approx.f32 %0, %1;" : "=f"(y) : "f"(x)); return y;
}
static __device__ __forceinline__ float fast_sig(float x) {
    return fast_rcp(1.0f + fast_exp2(-1.4426950408889634f * x));
}
static __device__ __forceinline__ float fast_tanh(float x) {
    return fmaf(2.0f, fast_sig(2.0f * x), -1.0f);
}

// ---------------- fp32 -> fp16 pre-convert (+ W gate-interleave permute) ----------------
__global__ void __launch_bounds__(256)
convert_kernel(const float* __restrict__ X,
               const float* __restrict__ Wfw,
               const float* __restrict__ Wbw)
{
    const int tid = threadIdx.x;
    if (blockIdx.x < 16384) {
        size_t e = ((size_t)blockIdx.x * 256 + tid) * 4;
        float4 v = *(const float4*)(X + e);
        __half* dst = g_Xh + e;
        ((__half2*)dst)[0] = __floats2half2_rn(v.x, v.y);
        ((__half2*)dst)[1] = __floats2half2_rn(v.z, v.w);
    } else {
        int blk2 = blockIdx.x - 16384;                 // 0..1535
        int wrow = blk2 * 2 + (tid >> 7);              // dest row 0..3071
        int j    = (tid & 127) * 4;
        int dir = wrow / NDIR;
        int rem = wrow % NDIR;
        int h = rem / 3, g = rem % 3;
        const float* src = (dir ? Wbw : Wfw) + ((size_t)(g * HID + h)) * DIN + j;
        float4 v = *(const float4*)src;
        __half* dst = g_Wh + (size_t)wrow * DIN + j;
        ((__half2*)dst)[0] = __floats2half2_rn(v.x, v.y);
        ((__half2*)dst)[1] = __floats2half2_rn(v.z, v.w);
    }
}

// ---------------- GEMM kernel (f16-acc HMMA + fp32 spill + fused act + 8-step scan) ----------------
// grid (32 n-tiles, 256 m-tiles), 256 thr, 2 CTA/SM, 3-stage cp.async
__global__ void __launch_bounds__(NTHREADS, 2)
gemm_kernel(const float* __restrict__ bfw, const float* __restrict__ bbw)
{
    extern __shared__ __half smem[];
    const int tid  = threadIdx.x;
    const int lane = tid & 31;
    const int wid  = tid >> 5;                 // 0..7
    const int gid  = lane >> 2;                // 0..7
    const int tig  = lane & 3;                 // 0..3
    const int warp_m = (wid >> 1) * 32;        // 0,32,64,96
    const int warp_n = (wid & 1) * 48;         // 0,48

    const int n0    = blockIdx.x * BN;         // within one dir (1536/96=16 tiles/dir)
    const int mtile = blockIdx.y;              // seq block: s in [8*mtile, 8*mtile+8)
    const int m0    = mtile * BM;

    const __half* Ag = g_Xh + (size_t)m0 * DIN;
    const __half* Bg = g_Wh + (size_t)n0 * DIN;

    const uint32_t sbase = smem_u32(smem);
    // per stage: A at +0 (128*128B=16KB), B at +16KB (96*128B=12KB)

    auto load_stage = [&](int kt) {
        const int k0 = kt * BK;
        const uint32_t sb = sbase + (kt % NSTAGE) * STAGE_BYTES;
        #pragma unroll
        for (int i = 0; i < 4; i++) {                          // A: 1024 chunks
            int idx = tid + i * NTHREADS;
            int row = idx >> 3, c16 = idx & 7;
            uint32_t off = row * 128 + ((c16 ^ (row & 7)) << 4);
            cp_async16(sb + off, Ag + (size_t)row * DIN + k0 + c16 * 8);
        }
        #pragma unroll
        for (int i = 0; i < 3; i++) {                          // B: 768 chunks
            int idx = tid + i * NTHREADS;
            int row = idx >> 3, c16 = idx & 7;
            uint32_t off = BM * 128 + row * 128 + ((c16 ^ (row & 7)) << 4);
            cp_async16(sb + off, Bg + (size_t)row * DIN + k0 + c16 * 8);
        }
        cp_commit();
    };

    float acc[2][6][4];
    #pragma unroll
    for (int mi = 0; mi < 2; mi++)
        #pragma unroll
        for (int ni = 0; ni < 6; ni++)
            #pragma unroll
            for (int k = 0; k < 4; k++) acc[mi][ni][k] = 0.0f;

    uint32_t hacc[2][6][2];
    #pragma unroll
    for (int mi = 0; mi < 2; mi++)
        #pragma unroll
        for (int ni = 0; ni < 6; ni++) {
            hacc[mi][ni][0] = 0u; hacc[mi][ni][1] = 0u;
        }

    const int lrow = lane & 15;
    const int lhi  = lane >> 4;
    uint32_t a_base[2], a_key[2];
    #pragma unroll
    for (int mi = 0; mi < 2; mi++) {
        int r = warp_m + mi * 16 + lrow;
        a_base[mi] = (uint32_t)r * 128;
        a_key[mi]  = r & 7;
    }
    uint32_t b_base[3], b_key[3];
    #pragma unroll
    for (int nj = 0; nj < 3; nj++) {
        int r = warp_n + nj * 16 + lrow;
        b_base[nj] = BM * 128 + (uint32_t)r * 128;
        b_key[nj]  = r & 7;
    }

    load_stage(0);
    load_stage(1);

    for (int kt = 0; kt < KTILES; kt++) {
        if (kt + 2 < KTILES)       { load_stage(kt + 2); cp_wait<2>(); }
        else if (kt + 2 == KTILES) { cp_wait<1>(); }
        else                       { cp_wait<0>(); }
        __syncthreads();

        const uint32_t sb = sbase + (kt % NSTAGE) * STAGE_BYTES;

        #pragma unroll
        for (int ks = 0; ks < 4; ks++) {
            const uint32_t c16 = (uint32_t)(ks * 2 + lhi);
            uint32_t a[2][4];
            #pragma unroll
            for (int mi = 0; mi < 2; mi++)
                ldsm_x4(a[mi], sb + a_base[mi] + ((c16 ^ a_key[mi]) << 4));
            uint32_t b[3][4];
            #pragma unroll
            for (int nj = 0; nj < 3; nj++)
                ldsm_x4(b[nj], sb + b_base[nj] + ((c16 ^ b_key[nj]) << 4));
            #pragma unroll
            for (int mi = 0; mi < 2; mi++)
                #pragma unroll
                for (int nj = 0; nj < 3; nj++) {
                    mma_f16acc(hacc[mi][2 * nj],     a[mi], b[nj][0], b[nj][2]);
                    mma_f16acc(hacc[mi][2 * nj + 1], a[mi], b[nj][1], b[nj][3]);
                }
        }

        // spill f16 partials into fp32 accumulators every 2 k-tiles (K=128)
        if (kt & 1) {
            #pragma unroll
            for (int mi = 0; mi < 2; mi++)
                #pragma unroll
                for (int ni = 0; ni < 6; ni++) {
                    float2 v0 = __half22float2(*(__half2*)&hacc[mi][ni][0]);
                    float2 v1 = __half22float2(*(__half2*)&hacc[mi][ni][1]);
                    acc[mi][ni][0] += v0.x;  acc[mi][ni][1] += v0.y;
                    acc[mi][ni][2] += v1.x;  acc[mi][ni][3] += v1.y;
                    hacc[mi][ni][0] = 0u;    hacc[mi][ni][1] = 0u;
                }
        }
        __syncthreads();
    }

    // ---- stage accs through smem ----
    float* sred = (float*)smem;                  // 128 x 100 pitch = 51.2KB
    #pragma unroll
    for (int mi = 0; mi < 2; mi++) {
        int r0 = warp_m + mi * 16 + gid;
        #pragma unroll
        for (int ni = 0; ni < 6; ni++) {
            int cl = warp_n + ni * 8 + tig * 2;
            *(float2*)(sred + r0 * EPIPITCH + cl) =
                make_float2(acc[mi][ni][0], acc[mi][ni][1]);
            *(float2*)(sred + (r0 + 8) * EPIPITCH + cl) =
                make_float2(acc[mi][ni][2], acc[mi][ni][3]);
        }
    }
    __syncthreads();

    // ---- fused activation + 8-step local scan ----
    const int hl   = tid & 31;
    const int bgr  = tid >> 5;                   // 0..7
    const int dir  = n0 / NDIR;
    const int hg   = (n0 % NDIR) / 3 + hl;
    const float* bias = dir ? bbw : bfw;
    const float bz = bias[hg];
    const float bf = bias[HID + hg];
    const float bo = bias[2 * HID + hg];
    const int chunk = dir ? (NCHUNK - 1 - mtile) : mtile;   // scan-order chunk id

    #pragma unroll
    for (int pass = 0; pass < 2; pass++) {
        const int b = bgr + pass * 8;
        float P = 1.0f, H = 0.0f;
        #pragma unroll
        for (int ii = 0; ii < 8; ii++) {
            const int s_local = dir ? (7 - ii) : ii;         // scan order
            const float* rp = sred + (s_local * 16 + b) * EPIPITCH + hl * 3;
            float z = fast_tanh(rp[0] + bz);
            float f = fast_sig(rp[1] + bf);
            float o = fast_sig(rp[2] + bo);
            float a = 1.0f - f;
            H = fmaf(a, H, f * z);
            P *= a;
            const int s = mtile * 8 + s_local;
            size_t idx = ((size_t)(s * BATCH + b) * 2 + dir) * HID + hg;
            g_ph[idx] = __floats2half2_rn(P, H);
            g_o[idx]  = __float2half_rn(o);
        }
        const int ch = dir * 8192 + b * 512 + hg;
        g_AC[(size_t)ch * NCHUNK + chunk] = make_float2(P, H);
    }
}

// ---------------- combine: chunk aggregates -> superchunk carry-ins ----------------
__global__ void __launch_bounds__(256)
combine_kernel()
{
    __shared__ float2 sAC[16][17];
    const int tid = threadIdx.x;
    const int cl  = tid >> 4;                    // channel-local 0..15
    const int sc  = tid & 15;                    // superchunk 0..15
    const int ch  = blockIdx.x * 16 + cl;

    const float4* p = (const float4*)(g_AC + (size_t)ch * NCHUNK + sc * 16);
    float SA = 1.0f, SC = 0.0f;
    #pragma unroll
    for (int q = 0; q < 8; q++) {
        float4 v = p[q];                         // (A0,C0,A1,C1)
        SC = fmaf(v.x, SC, v.y); SA *= v.x;
        SC = fmaf(v.z, SC, v.w); SA *= v.z;
    }
    sAC[cl][sc] = make_float2(SA, SC);
    __syncthreads();

    if (tid < 16) {
        const int c = tid;
        const int chh = blockIdx.x * 16 + c;
        float h = 0.0f;
        #pragma unroll
        for (int s = 0; s < NSUPER; s++) {
            g_hsup[(size_t)chh * NSUPER + s] = h;
            float2 v = sAC[c][s];
            h = fmaf(v.x, h, v.y);
        }
    }
}

// ---------------- final: apply carries, write output (strength-reduced) ----------------
// grid 2048 x 128: block = (channel-group of 128) x superchunk; 128 positions/thread
__global__ void __launch_bounds__(128)
final_kernel(float* __restrict__ out)
{
    const int sc  = blockIdx.x & 15;
    const int ch  = (blockIdx.x >> 4) * 128 + threadIdx.x;
    const int dir = ch >> 13;
    const int b   = (ch >> 9) & 15;
    const int hg  = ch & 511;

    float h = g_hsup[(size_t)ch * NSUPER + sc];

    const int p0      = sc * 128;                         // first scan-order position
    const int s_first = dir ? (SEQ - 1 - p0) : p0;
    const ptrdiff_t step = dir ? -(ptrdiff_t)SSTRIDE : (ptrdiff_t)SSTRIDE;

    const size_t idx0 = ((size_t)(s_first * BATCH + b) * 2 + dir) * HID + hg;
    const __half2* p  = g_ph + idx0;
    const __half*  po = g_o  + idx0;
    float* q = out + (size_t)s_first * SSTRIDE + b * (2 * HID) + dir * HID + hg;

    #pragma unroll 2
    for (int kl = 0; kl < 16; kl++) {
        float hs = h;
        #pragma unroll
        for (int i = 0; i < 8; i++) {
            float2 ph = __half22float2(*p);
            float o   = __half2float(*po);
            hs = fmaf(ph.x, h, ph.y);            // h_s = H_s + P_s * h_carry
            *q = o * hs;
            p += step; po += step; q += step;
        }
        h = hs;                                  // carry = last position's h
    }
}

// ---------------- launch ----------------
extern "C" void kernel_launch(void* const* d_in, const int* in_sizes, int n_in,
                              void* d_out, int out_size)
{
    (void)in_sizes; (void)n_in; (void)out_size;
    const float* X   = (const float*)d_in[0];
    const float* Wfw = (const float*)d_in[1];
    const float* bfw = (const float*)d_in[2];
    const float* Wbw = (const float*)d_in[3];
    const float* bbw = (const float*)d_in[4];
    float* out = (float*)d_out;

    cudaFuncSetAttribute(gemm_kernel,
                         cudaFuncAttributeMaxDynamicSharedMemorySize, SMEM_BYTES);

    convert_kernel<<<17920, 256>>>(X, Wfw, Wbw);
    gemm_kernel<<<dim3(32, 256), NTHREADS, SMEM_BYTES>>>(bfw, bbw);
    combine_kernel<<<NCH / 16, 256>>>();
    final_kernel<<<(NCH / 128) * NSUPER, 128>>>(out);
}

// round 17
// speedup vs baseline: 1.0603x; 1.0603x over previous
#include <cuda_runtime.h>
#include <cuda_fp16.h>
#include <cstdint>
#include <cstddef>

// ---------------- problem constants ----------------
#define SEQ   2048
#define BATCH 16
#define DIN   512
#define HID   512
#define MROWS (SEQ*BATCH)      // 32768 rows (s*16+b)
#define NDIR  (3*HID)          // 1536 gate cols per direction
#define NCOLS (2*NDIR)         // 3072 combined
#define XCNT  ((size_t)MROWS*DIN)

// ---------------- GEMM tiling (fp16 mma m16n8k16, f32 acc, fused epilogue+scan) ----------------
#define BM 128                 // = 8 seq steps x 16 batch
#define BN 96                  // 32 h * 3 gates (z,f,o interleaved)
#define BK 64                  // halves per k-tile (128B rows)
#define KTILES (DIN/BK)        // 8
#define NTHREADS 256
#define NSTAGE 3
#define STAGE_BYTES ((BM+BN)*BK*2)            // 28672
#define SMEM_BYTES  (NSTAGE*STAGE_BYTES)      // 86016 (epilogue reuse 128*100*4=51200)
#define EPIPITCH 100

// ---------------- scan chunking ----------------
#define NCH     16384          // dir*8192 + b*512 + h
#define NCHUNK  256            // chunks of 8 steps (one per m-tile)
#define NSUPER  16             // superchunks of 16 chunks (128 steps)
#define SSTRIDE (BATCH*2*HID)  // per-s element stride in g_ph/g_o/out (16384)

// ---------------- device scratch ----------------
__device__ __half  g_Xh[XCNT];                       // fp16 X
__device__ __half  g_Wh[(size_t)NCOLS * DIN];        // fp16 permuted [dir][h*3+g]
__device__ __half2 g_ph[(size_t)MROWS * 2 * HID];    // (P=prefix prod a, H=local h)
__device__ __half  g_o[(size_t)MROWS * 2 * HID];     // o gate
__device__ float2  g_AC[(size_t)NCH * NCHUNK];       // per-chunk (A,C), [ch][chunk]
__device__ float   g_hsup[(size_t)NCH * NSUPER];     // h at superchunk start

// ---------------- helpers ----------------
static __device__ __forceinline__ uint32_t smem_u32(const void* p) {
    uint32_t a;
    asm("{ .reg .u64 t; cvta.to.shared.u64 t, %1; cvt.u32.u64 %0, t; }"
        : "=r"(a) : "l"(p));
    return a;
}
static __device__ __forceinline__ void cp_async16(uint32_t saddr, const void* gaddr) {
    asm volatile("cp.async.cg.shared.global [%0], [%1], 16;"
                 :: "r"(saddr), "l"(gaddr) : "memory");
}
static __device__ __forceinline__ void cp_commit() {
    asm volatile("cp.async.commit_group;" ::: "memory");
}
template <int N>
static __device__ __forceinline__ void cp_wait() {
    asm volatile("cp.async.wait_group %0;" :: "n"(N) : "memory");
}
static __device__ __forceinline__ void ldsm_x4(uint32_t* r, uint32_t addr) {
    asm volatile("ldmatrix.sync.aligned.m8n8.x4.shared.b16 {%0,%1,%2,%3}, [%4];"
                 : "=r"(r[0]), "=r"(r[1]), "=r"(r[2]), "=r"(r[3]) : "r"(addr));
}
static __device__ __forceinline__ void mma_f16(float* d, const uint32_t* a,
                                               uint32_t b0, uint32_t b1) {
    asm volatile(
        "mma.sync.aligned.m16n8k16.row.col.f32.f16.f16.f32 "
        "{%0,%1,%2,%3}, {%4,%5,%6,%7}, {%8,%9}, {%0,%1,%2,%3};"
        : "+f"(d[0]), "+f"(d[1]), "+f"(d[2]), "+f"(d[3])
        : "r"(a[0]), "r"(a[1]), "r"(a[2]), "r"(a[3]), "r"(b0), "r"(b1));
}
static __device__ __forceinline__ float fast_exp2(float x) {
    float y; asm("ex2.approx.f32 %0, %1;" : "=f"(y) : "f"(x)); return y;
}
static __device__ __forceinline__ float fast_rcp(float x) {
    float y; asm("rcp.approx.f32 %0, %1;" : "=f"(y) : "f"(x)); return y;
}
static __device__ __forceinline__ float fast_sig(float x) {
    return fast_rcp(1.0f + fast_exp2(-1.4426950408889634f * x));
}
static __device__ __forceinline__ float fast_tanh(float x) {
    return fmaf(2.0f, fast_sig(2.0f * x), -1.0f);
}

// ---------------- fp32 -> fp16 pre-convert (+ W gate-interleave permute) ----------------
__global__ void __launch_bounds__(256)
convert_kernel(const float* __restrict__ X,
               const float* __restrict__ Wfw,
               const float* __restrict__ Wbw)
{
    const int tid = threadIdx.x;
    if (blockIdx.x < 16384) {
        size_t e = ((size_t)blockIdx.x * 256 + tid) * 4;
        float4 v = *(const float4*)(X + e);
        __half* dst = g_Xh + e;
        ((__half2*)dst)[0] = __floats2half2_rn(v.x, v.y);
        ((__half2*)dst)[1] = __floats2half2_rn(v.z, v.w);
    } else {
        int blk2 = blockIdx.x - 16384;                 // 0..1535
        int wrow = blk2 * 2 + (tid >> 7);              // dest row 0..3071
        int j    = (tid & 127) * 4;
        int dir = wrow / NDIR;
        int rem = wrow % NDIR;
        int h = rem / 3, g = rem % 3;
        const float* src = (dir ? Wbw : Wfw) + ((size_t)(g * HID + h)) * DIN + j;
        float4 v = *(const float4*)src;
        __half* dst = g_Wh + (size_t)wrow * DIN + j;
        ((__half2*)dst)[0] = __floats2half2_rn(v.x, v.y);
        ((__half2*)dst)[1] = __floats2half2_rn(v.z, v.w);
    }
}

// ---------------- GEMM kernel (fp16 HMMA f32-acc + fused activation + 8-step local scan) ----------------
// grid (32 n-tiles, 256 m-tiles), 256 thr, 2 CTA/SM, 3-stage cp.async
__global__ void __launch_bounds__(NTHREADS, 2)
gemm_kernel(const float* __restrict__ bfw, const float* __restrict__ bbw)
{
    extern __shared__ __half smem[];
    const int tid  = threadIdx.x;
    const int lane = tid & 31;
    const int wid  = tid >> 5;                 // 0..7
    const int gid  = lane >> 2;                // 0..7
    const int tig  = lane & 3;                 // 0..3
    const int warp_m = (wid >> 1) * 32;        // 0,32,64,96
    const int warp_n = (wid & 1) * 48;         // 0,48

    const int n0    = blockIdx.x * BN;         // within one dir (1536/96=16 tiles/dir)
    const int mtile = blockIdx.y;              // seq block: s in [8*mtile, 8*mtile+8)
    const int m0    = mtile * BM;

    const __half* Ag = g_Xh + (size_t)m0 * DIN;
    const __half* Bg = g_Wh + (size_t)n0 * DIN;

    const uint32_t sbase = smem_u32(smem);
    // per stage: A at +0 (128*128B=16KB), B at +16KB (96*128B=12KB)

    auto load_stage = [&](int kt) {
        const int k0 = kt * BK;
        const uint32_t sb = sbase + (kt % NSTAGE) * STAGE_BYTES;
        #pragma unroll
        for (int i = 0; i < 4; i++) {                          // A: 1024 chunks
            int idx = tid + i * NTHREADS;
            int row = idx >> 3, c16 = idx & 7;
            uint32_t off = row * 128 + ((c16 ^ (row & 7)) << 4);
            cp_async16(sb + off, Ag + (size_t)row * DIN + k0 + c16 * 8);
        }
        #pragma unroll
        for (int i = 0; i < 3; i++) {                          // B: 768 chunks
            int idx = tid + i * NTHREADS;
            int row = idx >> 3, c16 = idx & 7;
            uint32_t off = BM * 128 + row * 128 + ((c16 ^ (row & 7)) << 4);
            cp_async16(sb + off, Bg + (size_t)row * DIN + k0 + c16 * 8);
        }
        cp_commit();
    };

    float acc[2][6][4];
    #pragma unroll
    for (int mi = 0; mi < 2; mi++)
        #pragma unroll
        for (int ni = 0; ni < 6; ni++)
            #pragma unroll
            for (int k = 0; k < 4; k++) acc[mi][ni][k] = 0.0f;

    const int lrow = lane & 15;
    const int lhi  = lane >> 4;
    uint32_t a_base[2], a_key[2];
    #pragma unroll
    for (int mi = 0; mi < 2; mi++) {
        int r = warp_m + mi * 16 + lrow;
        a_base[mi] = (uint32_t)r * 128;
        a_key[mi]  = r & 7;
    }
    uint32_t b_base[3], b_key[3];
    #pragma unroll
    for (int nj = 0; nj < 3; nj++) {
        int r = warp_n + nj * 16 + lrow;
        b_base[nj] = BM * 128 + (uint32_t)r * 128;
        b_key[nj]  = r & 7;
    }

    load_stage(0);
    load_stage(1);

    for (int kt = 0; kt < KTILES; kt++) {
        if (kt + 2 < KTILES)       { load_stage(kt + 2); cp_wait<2>(); }
        else if (kt + 2 == KTILES) { cp_wait<1>(); }
        else                       { cp_wait<0>(); }
        __syncthreads();

        const uint32_t sb = sbase + (kt % NSTAGE) * STAGE_BYTES;

        #pragma unroll
        for (int ks = 0; ks < 4; ks++) {
            const uint32_t c16 = (uint32_t)(ks * 2 + lhi);
            uint32_t a[2][4];
            #pragma unroll
            for (int mi = 0; mi < 2; mi++)
                ldsm_x4(a[mi], sb + a_base[mi] + ((c16 ^ a_key[mi]) << 4));
            uint32_t b[3][4];
            #pragma unroll
            for (int nj = 0; nj < 3; nj++)
                ldsm_x4(b[nj], sb + b_base[nj] + ((c16 ^ b_key[nj]) << 4));
            #pragma unroll
            for (int mi = 0; mi < 2; mi++)
                #pragma unroll
                for (int nj = 0; nj < 3; nj++) {
                    mma_f16(acc[mi][2 * nj],     a[mi], b[nj][0], b[nj][2]);
                    mma_f16(acc[mi][2 * nj + 1], a[mi], b[nj][1], b[nj][3]);
                }
        }
        __syncthreads();
    }

    // ---- stage accs through smem ----
    float* sred = (float*)smem;                  // 128 x 100 pitch = 51.2KB
    #pragma unroll
    for (int mi = 0; mi < 2; mi++) {
        int r0 = warp_m + mi * 16 + gid;
        #pragma unroll
        for (int ni = 0; ni < 6; ni++) {
            int cl = warp_n + ni * 8 + tig * 2;
            *(float2*)(sred + r0 * EPIPITCH + cl) =
                make_float2(acc[mi][ni][0], acc[mi][ni][1]);
            *(float2*)(sred + (r0 + 8) * EPIPITCH + cl) =
                make_float2(acc[mi][ni][2], acc[mi][ni][3]);
        }
    }
    __syncthreads();

    // ---- fused activation + 8-step local scan ----
    const int hl   = tid & 31;
    const int bgr  = tid >> 5;                   // 0..7
    const int dir  = n0 / NDIR;
    const int hg   = (n0 % NDIR) / 3 + hl;
    const float* bias = dir ? bbw : bfw;
    const float bz = bias[hg];
    const float bf = bias[HID + hg];
    const float bo = bias[2 * HID + hg];
    const int chunk = dir ? (NCHUNK - 1 - mtile) : mtile;   // scan-order chunk id

    #pragma unroll
    for (int pass = 0; pass < 2; pass++) {
        const int b = bgr + pass * 8;
        float P = 1.0f, H = 0.0f;
        #pragma unroll
        for (int ii = 0; ii < 8; ii++) {
            const int s_local = dir ? (7 - ii) : ii;         // scan order
            const float* rp = sred + (s_local * 16 + b) * EPIPITCH + hl * 3;
            float z = fast_tanh(rp[0] + bz);
            float f = fast_sig(rp[1] + bf);
            float o = fast_sig(rp[2] + bo);
            float a = 1.0f - f;
            H = fmaf(a, H, f * z);
            P *= a;
            const int s = mtile * 8 + s_local;
            size_t idx = ((size_t)(s * BATCH + b) * 2 + dir) * HID + hg;
            g_ph[idx] = __floats2half2_rn(P, H);
            g_o[idx]  = __float2half_rn(o);
        }
        const int ch = dir * 8192 + b * 512 + hg;
        g_AC[(size_t)ch * NCHUNK + chunk] = make_float2(P, H);
    }
}

// ---------------- combine: chunk aggregates -> superchunk carry-ins ----------------
__global__ void __launch_bounds__(256)
combine_kernel()
{
    __shared__ float2 sAC[16][17];
    const int tid = threadIdx.x;
    const int cl  = tid >> 4;                    // channel-local 0..15
    const int sc  = tid & 15;                    // superchunk 0..15
    const int ch  = blockIdx.x * 16 + cl;

    const float4* p = (const float4*)(g_AC + (size_t)ch * NCHUNK + sc * 16);
    float SA = 1.0f, SC = 0.0f;
    #pragma unroll
    for (int q = 0; q < 8; q++) {
        float4 v = p[q];                         // (A0,C0,A1,C1)
        SC = fmaf(v.x, SC, v.y); SA *= v.x;
        SC = fmaf(v.z, SC, v.w); SA *= v.z;
    }
    sAC[cl][sc] = make_float2(SA, SC);
    __syncthreads();

    if (tid < 16) {
        const int c = tid;
        const int chh = blockIdx.x * 16 + c;
        float h = 0.0f;
        #pragma unroll
        for (int s = 0; s < NSUPER; s++) {
            g_hsup[(size_t)chh * NSUPER + s] = h;
            float2 v = sAC[c][s];
            h = fmaf(v.x, h, v.y);
        }
    }
}

// ---------------- final: apply carries, write output (strength-reduced, deep unroll) ----------------
// grid 2048 x 128: block = (channel-group of 128) x superchunk; 128 positions/thread
__global__ void __launch_bounds__(128)
final_kernel(float* __restrict__ out)
{
    const int sc  = blockIdx.x & 15;
    const int ch  = (blockIdx.x >> 4) * 128 + threadIdx.x;
    const int dir = ch >> 13;
    const int b   = (ch >> 9) & 15;
    const int hg  = ch & 511;

    float h = g_hsup[(size_t)ch * NSUPER + sc];

    const int p0      = sc * 128;                         // first scan-order position
    const int s_first = dir ? (SEQ - 1 - p0) : p0;
    const ptrdiff_t step = dir ? -(ptrdiff_t)SSTRIDE : (ptrdiff_t)SSTRIDE;

    const size_t idx0 = ((size_t)(s_first * BATCH + b) * 2 + dir) * HID + hg;
    const __half2* p  = g_ph + idx0;
    const __half*  po = g_o  + idx0;
    float* q = out + (size_t)s_first * SSTRIDE + b * (2 * HID) + dir * HID + hg;

    #pragma unroll 4
    for (int kl = 0; kl < 16; kl++) {
        float hs = h;
        #pragma unroll
        for (int i = 0; i < 8; i++) {
            float2 ph = __half22float2(*p);
            float o   = __half2float(*po);
            hs = fmaf(ph.x, h, ph.y);            // h_s = H_s + P_s * h_carry
            *q = o * hs;
            p += step; po += step; q += step;
        }
        h = hs;                                  // carry = last position's h
    }
}

// ---------------- launch ----------------
extern "C" void kernel_launch(void* const* d_in, const int* in_sizes, int n_in,
                              void* d_out, int out_size)
{
    (void)in_sizes; (void)n_in; (void)out_size;
    const float* X   = (const float*)d_in[0];
    const float* Wfw = (const float*)d_in[1];
    const float* bfw = (const float*)d_in[2];
    const float* Wbw = (const float*)d_in[3];
    const float* bbw = (const float*)d_in[4];
    float* out = (float*)d_out;

    cudaFuncSetAttribute(gemm_kernel,
                         cudaFuncAttributeMaxDynamicSharedMemorySize, SMEM_BYTES);

    convert_kernel<<<17920, 256>>>(X, Wfw, Wbw);
    gemm_kernel<<<dim3(32, 256), NTHREADS, SMEM_BYTES>>>(bfw, bbw);
    combine_kernel<<<NCH / 16, 256>>>();
    final_kernel<<<(NCH / 128) * NSUPER, 128>>>(out);
}